// round 17
// baseline (speedup 1.0000x reference)
#include <cuda_runtime.h>

// Fused SSIM loss. pred/target: [32,1,512,512] f32, WIN=11 VALID -> 502x502.
// out[0] = 1 - mean(S).
//
// R13: 8 cols/thread (TPB=64) to amortize the fixed 10-col halo cost over
// twice the outputs: LDS wavefronts per output col drop ~55% (L1 staging
// traffic was ~2/3 of runtime by wavefront accounting). Swizzled staging
// (R2-proven), 4 box filters, depth-2 prefetch, 1 barrier/row (2-warp
// barriers), 1152-block single wave at 8 blocks/SM.

#define BATCH   32
#define HH      512
#define WW      512
#define WIN     11
#define OHH     502
#define OWW     502
#define NBANDS  36
#define RPB     14
#define TPB     64
#define NBLK    (BATCH * NBANDS)   // 1152

__device__ float        g_partial[NBLK];
__device__ unsigned int g_count = 0;

// XOR swizzle on float4 index: breaks the 8-way bank conflict of stride-2
// float4 access down to ~conflict-free (verified in R2).
__device__ __forceinline__ int swz(int i4) { return i4 ^ ((i4 >> 3) & 7); }

__global__ __launch_bounds__(TPB, 8) void ssim_main(const float* __restrict__ pred,
                                                    const float* __restrict__ targ,
                                                    float* __restrict__ out)
{
    const int band = blockIdx.x;
    const int img  = blockIdx.y;
    const int r0   = band * RPB;
    int rend = r0 + RPB - 1;
    if (rend > OHH - 1) rend = OHH - 1;

    const int t = threadIdx.x;          // 0..63
    const int c = t << 3;               // 8 cols per thread, c in [0,504]

    // Double-buffered staging of 4 vertical-sum rows, swizzled float4 layout.
    // Swizzled store/load indices stay in [0,127]; pads 128..131 are fixed
    // points of swz() and zeroed once.
    __shared__ float4 sv[2][4][132];
    __shared__ float  wsum[2];
    __shared__ int    is_last;
    __shared__ double dred[TPB];

    {
        const float4 z4 = make_float4(0.f, 0.f, 0.f, 0.f);
        if (t < 32) {                   // 2 buf * 4 q * 4 pad entries
            int b = t / 16, rem = t % 16;
            sv[b][rem / 4][128 + (rem & 3)] = z4;
        }
    }

    // Loop-invariant swizzled indices.
    const int i_s0 = swz(2 * t);
    const int i_s1 = swz(2 * t + 1);
    const int i_l0 = swz(2 * t + 2);
    const int i_l1 = swz(2 * t + 3);
    const int i_l2 = swz(2 * t + 4);

    const float* pb = pred + img * (HH * WW);
    const float* qb = targ + img * (HH * WW);

    // Vertical sliding sums: s0=Sx, s1=Sy, s2=S(x^2+y^2), s3=Sxy.
    float s[4][8];
#pragma unroll
    for (int q = 0; q < 4; ++q)
#pragma unroll
        for (int j = 0; j < 8; ++j) s[q][j] = 0.f;

    // Warm-up: rows r0 .. r0+9.
    for (int rr = r0; rr < r0 + WIN - 1; ++rr) {
        const float4 p0 = *(const float4*)(pb + rr * WW + c);
        const float4 p1 = *(const float4*)(pb + rr * WW + c + 4);
        const float4 q0 = *(const float4*)(qb + rr * WW + c);
        const float4 q1 = *(const float4*)(qb + rr * WW + c + 4);
        const float pj[8] = {p0.x,p0.y,p0.z,p0.w,p1.x,p1.y,p1.z,p1.w};
        const float qj[8] = {q0.x,q0.y,q0.z,q0.w,q1.x,q1.y,q1.z,q1.w};
#pragma unroll
        for (int j = 0; j < 8; ++j) {
            s[0][j] += pj[j];
            s[1][j] += qj[j];
            s[2][j] = fmaf(pj[j], pj[j], fmaf(qj[j], qj[j], s[2][j]));
            s[3][j] = fmaf(pj[j], qj[j], s[3][j]);
        }
    }

    const float inv_np = 1.0f / 121.0f;
    const float k120   = 1.0f / 120.0f;     // cov_norm / NP
    const float cn     = 121.0f / 120.0f;   // cov_norm
    const float C1     = 1.0e-4f;
    const float C2     = 9.0e-4f;

    float acc = 0.0f;

    // Depth-2 pipeline prologue: rows r0+10 and r0+11 in flight.
    float4 pnA0 = *(const float4*)(pb + (r0 + WIN - 1) * WW + c);
    float4 pnA1 = *(const float4*)(pb + (r0 + WIN - 1) * WW + c + 4);
    float4 qnA0 = *(const float4*)(qb + (r0 + WIN - 1) * WW + c);
    float4 qnA1 = *(const float4*)(qb + (r0 + WIN - 1) * WW + c + 4);
    float4 pnB0 = *(const float4*)(pb + (r0 + WIN) * WW + c);
    float4 pnB1 = *(const float4*)(pb + (r0 + WIN) * WW + c + 4);
    float4 qnB0 = *(const float4*)(qb + (r0 + WIN) * WW + c);
    float4 qnB1 = *(const float4*)(qb + (r0 + WIN) * WW + c + 4);

    for (int orow = r0; orow <= rend; ++orow) {
        const int par = orow & 1;

        // Old top row (consumed at iteration end -> latency hidden).
        const float4 po0 = *(const float4*)(pb + orow * WW + c);
        const float4 po1 = *(const float4*)(pb + orow * WW + c + 4);
        const float4 qo0 = *(const float4*)(qb + orow * WW + c);
        const float4 qo1 = *(const float4*)(qb + orow * WW + c + 4);

        {   // add prefetched new row -> s covers rows orow..orow+10
            const float pj[8] = {pnA0.x,pnA0.y,pnA0.z,pnA0.w,pnA1.x,pnA1.y,pnA1.z,pnA1.w};
            const float qj[8] = {qnA0.x,qnA0.y,qnA0.z,qnA0.w,qnA1.x,qnA1.y,qnA1.z,qnA1.w};
#pragma unroll
            for (int j = 0; j < 8; ++j) {
                s[0][j] += pj[j];
                s[1][j] += qj[j];
                s[2][j] = fmaf(pj[j], pj[j], fmaf(qj[j], qj[j], s[2][j]));
                s[3][j] = fmaf(qj[j], pj[j], s[3][j]);
            }
        }

        // Stage vertical sums (swizzled).
#pragma unroll
        for (int q = 0; q < 4; ++q) {
            sv[par][q][i_s0] = make_float4(s[q][0], s[q][1], s[q][2], s[q][3]);
            sv[par][q][i_s1] = make_float4(s[q][4], s[q][5], s[q][6], s[q][7]);
        }

        // Rotate pipeline; issue distance-2 loads (row orow+12, clamped).
        pnA0 = pnB0; pnA1 = pnB1; qnA0 = qnB0; qnA1 = qnB1;
        {
            int rn = orow + WIN + 1;
            if (rn > HH - 1) rn = HH - 1;
            pnB0 = *(const float4*)(pb + rn * WW + c);
            pnB1 = *(const float4*)(pb + rn * WW + c + 4);
            qnB0 = *(const float4*)(qb + rn * WW + c);
            qnB1 = *(const float4*)(qb + rn * WW + c + 4);
        }

        __syncthreads();

        // Horizontal 11-window sliding sums; own 8 from registers, halo
        // (cols c+8..c+17) from smem: 2 LDS.128 + 1 LDS.64 per quantity.
        float w[4][8];
#pragma unroll
        for (int q = 0; q < 4; ++q) {
            const float4 A = sv[par][q][i_l0];          // cols c+8..c+11
            const float4 B = sv[par][q][i_l1];          // cols c+12..c+15
            const float2 C = *(const float2*)&sv[par][q][i_l2]; // c+16,c+17
            float w0 = ((s[q][0] + s[q][1]) + (s[q][2] + s[q][3]))
                     + ((s[q][4] + s[q][5]) + (s[q][6] + s[q][7]))
                     + (A.x + A.y) + A.z;               // cols c..c+10
            w[q][0] = w0;
            w[q][1] = w0      - s[q][0] + A.w;
            w[q][2] = w[q][1] - s[q][1] + B.x;
            w[q][3] = w[q][2] - s[q][2] + B.y;
            w[q][4] = w[q][3] - s[q][3] + B.z;
            w[q][5] = w[q][4] - s[q][4] + B.w;
            w[q][6] = w[q][5] - s[q][5] + C.x;
            w[q][7] = w[q][6] - s[q][6] + C.y;
        }

        // SSIM per output pixel.
#pragma unroll
        for (int j = 0; j < 8; ++j) {
            const float ux  = w[0][j] * inv_np;
            const float uy  = w[1][j] * inv_np;
            const float uxy = ux * uy;
            const float sq  = fmaf(ux, ux, uy * uy);
            const float A1  = fmaf(2.0f, uxy, C1);
            const float B1  = sq + C1;
            const float vxy = fmaf(w[3][j], k120, -cn * uxy);
            const float vs  = fmaf(w[2][j], k120, -cn * sq);   // vx + vy
            const float A2  = fmaf(2.0f, vxy, C2);
            const float B2  = vs + C2;
            const float S   = __fdividef(A1 * A2, B1 * B2);
            if (c + j < OWW) acc += S;
        }

        {   // subtract old top row -> s covers orow+1..orow+10
            const float uj[8] = {po0.x,po0.y,po0.z,po0.w,po1.x,po1.y,po1.z,po1.w};
            const float vj[8] = {qo0.x,qo0.y,qo0.z,qo0.w,qo1.x,qo1.y,qo1.z,qo1.w};
#pragma unroll
            for (int j = 0; j < 8; ++j) {
                s[0][j] -= uj[j];
                s[1][j] -= vj[j];
                s[2][j] = fmaf(-uj[j], uj[j], fmaf(-vj[j], vj[j], s[2][j]));
                s[3][j] = fmaf(-vj[j], uj[j], s[3][j]);
            }
        }
    }

    // Block reduction (2 warps).
    float v = acc;
#pragma unroll
    for (int off = 16; off; off >>= 1)
        v += __shfl_xor_sync(0xffffffffu, v, off);
    const int lane = t & 31, wid = t >> 5;
    if (lane == 0) wsum[wid] = v;
    __syncthreads();

    if (t == 0) {
        g_partial[img * NBANDS + band] = wsum[0] + wsum[1];
        __threadfence();
        const unsigned int tick = atomicAdd(&g_count, 1u);
        is_last = (tick == NBLK - 1);
    }
    __syncthreads();

    // Last block performs the deterministic final reduction.
    if (is_last) {
        __threadfence();
        double sd = 0.0;
        for (int i = t; i < NBLK; i += TPB)   // fixed slots, fixed order
            sd += (double)g_partial[i];
        dred[t] = sd;
        __syncthreads();
#pragma unroll
        for (int st = TPB / 2; st > 0; st >>= 1) {
            if (t < st) dred[t] += dred[t + st];
            __syncthreads();
        }
        if (t == 0) {
            out[0] = (float)(1.0 - dred[0] / ((double)BATCH * OHH * OWW));
            g_count = 0;   // reset for next graph replay
        }
    }
}

extern "C" void kernel_launch(void* const* d_in, const int* in_sizes, int n_in,
                              void* d_out, int out_size)
{
    const float* pred = (const float*)d_in[0];
    const float* targ = (const float*)d_in[1];
    float* out = (float*)d_out;

    ssim_main<<<dim3(NBANDS, BATCH), TPB>>>(pred, targ, out);
}